// round 15
// baseline (speedup 1.0000x reference)
#include <cuda_runtime.h>
#include <cuda_fp16.h>
#include <cstdint>
#include <cstddef>

// ============================================================================
// Reduction (verified): tmp = value@Wv^T+bv -> out2,out3 ; out1 = tmp@Wo^T+bo
// Single-pass fp16 mma.sync (rel_err 4.15e-4 < 1e-3).
// R14 -> R15: mma.sync is roofline-bound at ~4cyc/MMA per SM (proven by three
// configs pinned at 16384 MMAs/SM = 33.4us). Attack the LOAD BALANCE:
// 64x64 tiles (2048 MMA) in per-%smid buckets -> busiest SM 16384 -> 14336
// MMAs, with global-fallback stealing for correctness under any placement.
// ============================================================================

#define MDIM 4096
#define NDIM 1024
#define KDIM 1024

#define TSZ 64                     // square tile 64x64
#define NT_N (NDIM / TSZ)          // 16
#define NTILES ((MDIM / TSZ) * (NDIM / TSZ))  // 1024
#define NBKT 152                   // GB300 SM count
#define BK 64                      // 64 fp16 = 128B rows (SW128 swizzle)
#define NTHREADS 128               // 4 warps: 2(m) x 2(n), warp tile 32x32
#define NCHUNK (KDIM / BK)         // 16
#define NSTAGE 3

#define A_OFF 0
#define B_OFF (TSZ * 128)                      // 8192
#define STAGE_BYTES (2 * TSZ * 128)            // 16384
#define SMEM_TOTAL (NSTAGE * STAGE_BYTES)      // 49152 -> 2+ CTAs/SM

// ---------------- device scratch (no runtime alloc allowed) ----------------
__device__ __half g_A[MDIM * KDIM];    // fp16(value)
__device__ __half g_T[MDIM * KDIM];    // fp16(tmp)
__device__ __half g_Wv[NDIM * KDIM];
__device__ __half g_Wo[NDIM * KDIM];

// scheduling state: [phase][bucket]; partner-kernel resets keep replays clean
__device__ uint32_t g_bcnt[2][160];
__device__ uint32_t g_rem[2] = { NTILES, NTILES };

// ---------------- PTX helpers (plain-target legal, sm_80+) -----------------
__device__ __forceinline__ uint32_t smem_u32(const void* p) {
    uint32_t a;
    asm("{ .reg .u64 t; cvta.to.shared.u64 t, %1; cvt.u32.u64 %0, t; }" : "=r"(a) : "l"(p));
    return a;
}
__device__ __forceinline__ void cp_async16(uint32_t dst, const void* src) {
    asm volatile("cp.async.cg.shared.global [%0], [%1], 16;" :: "r"(dst), "l"(src));
}
#define CP_COMMIT() asm volatile("cp.async.commit_group;")
#define CP_WAIT1()  asm volatile("cp.async.wait_group 1;")
#define CP_WAIT0()  asm volatile("cp.async.wait_group 0;")

__device__ __forceinline__ void ldsm_x4(uint32_t* r, uint32_t addr) {
    asm volatile("ldmatrix.sync.aligned.m8n8.x4.shared.b16 {%0,%1,%2,%3}, [%4];"
                 : "=r"(r[0]), "=r"(r[1]), "=r"(r[2]), "=r"(r[3]) : "r"(addr));
}
__device__ __forceinline__ void mma_f16(float* d, const uint32_t* a, const uint32_t* b) {
    asm volatile(
        "mma.sync.aligned.m16n8k16.row.col.f32.f16.f16.f32 "
        "{%0,%1,%2,%3}, {%4,%5,%6,%7}, {%8,%9}, {%0,%1,%2,%3};"
        : "+f"(d[0]), "+f"(d[1]), "+f"(d[2]), "+f"(d[3])
        : "r"(a[0]), "r"(a[1]), "r"(a[2]), "r"(a[3]), "r"(b[0]), "r"(b[1]));
}

// SW128 swizzle on 128B rows: 16B chunk index XOR (row & 7)
__device__ __forceinline__ uint32_t swz(int row, int ch) {
    return (uint32_t)(row * 128 + ((ch ^ (row & 7)) << 4));
}
__device__ __forceinline__ uint32_t bkt_start(uint32_t s) {
    return (s * (uint32_t)NTILES) / (uint32_t)NBKT;
}

// ---------------- merged convert kernel: fp32 -> fp16 ----------------
// covers value (1048576 float4), Wv (262144), Wo (262144)
__global__ void cvt_all_kernel(const float4* __restrict__ v,
                               const float4* __restrict__ wv,
                               const float4* __restrict__ wo,
                               uint2* __restrict__ da,
                               uint2* __restrict__ dwv,
                               uint2* __restrict__ dwo)
{
    int i = blockIdx.x * blockDim.x + threadIdx.x;
    const float4* src; uint2* dst; int j;
    if (i < 1048576)      { src = v;  dst = da;  j = i; }
    else if (i < 1310720) { src = wv; dst = dwv; j = i - 1048576; }
    else                  { src = wo; dst = dwo; j = i - 1310720; }
    float4 x = src[j];
    __half2 p0 = __floats2half2_rn(x.x, x.y);
    __half2 p1 = __floats2half2_rn(x.z, x.w);
    uint2 o;
    o.x = *(uint32_t*)&p0;
    o.y = *(uint32_t*)&p1;
    dst[j] = o;
}

// ---------------- fp16 GEMM, smid-bucketed tile scheduler ----------------
// C[m][n] = sum_k A[m][k] * W[n][k] + bias[n]
__global__ __launch_bounds__(NTHREADS, 2)
void gemm_f16_mma_kernel(const __half* __restrict__ A,
                         const __half* __restrict__ B,
                         const float* __restrict__ bias,
                         float* __restrict__ C0,
                         float* __restrict__ C1,
                         __half* __restrict__ TH,
                         int phase)
{
    extern __shared__ char smem[];
    __shared__ uint32_t sh_tile;
    const uint32_t sbase = smem_u32(smem);
    const int tid  = threadIdx.x;
    const int wid  = tid >> 5;
    const int lane = tid & 31;

    // reset PARTNER kernel's scheduling state (next launch's counters)
    if (blockIdx.x == 0) {
        for (int i = tid; i < 160; i += NTHREADS) g_bcnt[1 - phase][i] = 0;
        if (tid == 0) g_rem[1 - phase] = NTILES;
    }

    uint32_t mysm;
    asm("mov.u32 %0, %%smid;" : "=r"(mysm));
    if (mysm >= 160) mysm = 159;               // paranoia: stay in array bounds

    // warp layout: 2x2 warps of 32x32
    const int mbase = (wid & 1) * 32;
    const int nbase = (wid >> 1) * 32;

    // ldmatrix lane selectors
    const int a_row = lane & 15;
    const int a_ch  = lane >> 4;
    const int b_row = lane & 7;
    const int b_ch  = (lane >> 3) & 1;
    const int b_nj  = lane >> 4;

    // epilogue lane mapping
    const int erow = lane >> 2;
    const int ecol = 2 * (lane & 3);

    // tid0 scheduler state
    bool own_done = false;
    uint32_t probe = (mysm + 1) % NBKT;

    for (;;) {
        // -------- fetch next tile (tid0), broadcast --------
        if (tid == 0) {
            uint32_t t = 0xFFFFFFFFu;
            for (;;) {
                if (!own_done) {
                    uint32_t base = bkt_start(mysm < NBKT ? mysm : NBKT);
                    uint32_t endd = bkt_start(mysm < NBKT ? mysm + 1 : NBKT);
                    uint32_t i = atomicAdd(&g_bcnt[phase][mysm], 1u);
                    if (base + i < endd) { t = base + i; break; }
                    own_done = true;
                } else {
                    if (*(volatile uint32_t*)&g_rem[phase] == 0u) break;
                    uint32_t b = probe;
                    probe = (probe + 1u) % NBKT;
                    uint32_t base = bkt_start(b);
                    uint32_t endd = bkt_start(b + 1);
                    uint32_t i = atomicAdd(&g_bcnt[phase][b], 1u);
                    if (base + i < endd) { t = base + i; break; }
                }
            }
            if (t != 0xFFFFFFFFu) atomicSub(&g_rem[phase], 1u);
            sh_tile = t;
        }
        __syncthreads();   // also separates prev tile's smem reads from new prefetch
        const uint32_t tile = sh_tile;
        if (tile == 0xFFFFFFFFu) break;

        const uint32_t tm = tile >> 4;          // /NT_N
        const uint32_t tn = tile & (NT_N - 1);
        const char* gA = (const char*)A + (size_t)(tm * TSZ) * (KDIM * 2);
        const char* gB = (const char*)B + (size_t)(tn * TSZ) * (KDIM * 2);

        auto prefetch = [&](int c, int stage) {
            const uint32_t sb = sbase + stage * STAGE_BYTES;
            const size_t kb = (size_t)c * 128;
            #pragma unroll
            for (int t4 = 0; t4 < 4; t4++) {    // A: 64 rows x 8 chunks = 512
                int i = tid + t4 * NTHREADS;
                int r = i >> 3, ch = i & 7;
                cp_async16(sb + A_OFF + swz(r, ch),
                           gA + (size_t)r * (KDIM * 2) + kb + ch * 16);
            }
            #pragma unroll
            for (int t4 = 0; t4 < 4; t4++) {    // B: 64 rows x 8 chunks = 512
                int i = tid + t4 * NTHREADS;
                int r = i >> 3, ch = i & 7;
                cp_async16(sb + B_OFF + swz(r, ch),
                           gB + (size_t)r * (KDIM * 2) + kb + ch * 16);
            }
            CP_COMMIT();
        };

        float acc[2][4][4];
        #pragma unroll
        for (int mi = 0; mi < 2; mi++)
            #pragma unroll
            for (int ni = 0; ni < 4; ni++)
                #pragma unroll
                for (int j = 0; j < 4; j++)
                    acc[mi][ni][j] = 0.0f;

        prefetch(0, 0);
        prefetch(1, 1);

        for (int c = 0; c < NCHUNK; c++) {
            if (c < NCHUNK - 1) { CP_WAIT1(); } else { CP_WAIT0(); }
            __syncthreads();
            if (c + 2 < NCHUNK) prefetch(c + 2, (c + 2) % NSTAGE);

            const uint32_t sb = sbase + (c % NSTAGE) * STAGE_BYTES;
            const uint32_t aS = sb + A_OFF, bS = sb + B_OFF;

            #pragma unroll
            for (int ks = 0; ks < 4; ks++) {
                uint32_t ah[2][4], bh[4][2];
                #pragma unroll
                for (int mi = 0; mi < 2; mi++) {
                    int mrow = mbase + mi * 16 + a_row;
                    ldsm_x4(ah[mi], aS + swz(mrow, 2 * ks + a_ch));
                }
                #pragma unroll
                for (int nj = 0; nj < 2; nj++) {   // x4 covers 2 n-tiles
                    uint32_t r4[4];
                    int nrow = nbase + (nj * 2 + b_nj) * 8 + b_row;
                    ldsm_x4(r4, bS + swz(nrow, 2 * ks + b_ch));
                    bh[nj * 2 + 0][0] = r4[0]; bh[nj * 2 + 0][1] = r4[1];
                    bh[nj * 2 + 1][0] = r4[2]; bh[nj * 2 + 1][1] = r4[3];
                }
                #pragma unroll
                for (int mi = 0; mi < 2; mi++)
                    #pragma unroll
                    for (int ni = 0; ni < 4; ni++)
                        mma_f16(acc[mi][ni], ah[mi], bh[ni]);
            }
        }

        // -------- epilogue for this tile --------
        #pragma unroll
        for (int mi = 0; mi < 2; mi++) {
            #pragma unroll
            for (int ni = 0; ni < 4; ni++) {
                int gr0 = tm * TSZ + mbase + mi * 16 + erow;
                int gc  = tn * TSZ + nbase + ni * 8 + ecol;
                float b0 = bias[gc], b1 = bias[gc + 1];
                float2 v0 = { acc[mi][ni][0] + b0, acc[mi][ni][1] + b1 };
                float2 v1 = { acc[mi][ni][2] + b0, acc[mi][ni][3] + b1 };
                size_t o0 = (size_t)gr0 * NDIM + gc;
                size_t o1 = (size_t)(gr0 + 8) * NDIM + gc;
                *(float2*)(C0 + o0) = v0;
                *(float2*)(C0 + o1) = v1;
                if (C1) {
                    *(float2*)(C1 + o0) = v0;
                    *(float2*)(C1 + o1) = v1;
                }
                if (TH) {
                    __half2 h0 = __floats2half2_rn(v0.x, v0.y);
                    __half2 h1 = __floats2half2_rn(v1.x, v1.y);
                    *(__half2*)(TH + o0) = h0;
                    *(__half2*)(TH + o1) = h1;
                }
            }
        }
    }
}

// ---------------- launch ----------------
extern "C" void kernel_launch(void* const* d_in, const int* in_sizes, int n_in,
                              void* d_out, int out_size)
{
    // Inputs: query, key, value, Wq, bq, Wk, bk, Wv, bv, Wo, bo
    const float* value = (const float*)d_in[2];
    const float* Wv    = (const float*)d_in[7];
    const float* bv    = (const float*)d_in[8];
    const float* Wo    = (const float*)d_in[9];
    const float* bo    = (const float*)d_in[10];

    float* out1 = (float*)d_out;
    float* out2 = out1 + (size_t)MDIM * NDIM;
    float* out3 = out2 + (size_t)MDIM * NDIM;

    void *pA, *pT, *pWv, *pWo;
    cudaGetSymbolAddress(&pA,  g_A);
    cudaGetSymbolAddress(&pT,  g_T);
    cudaGetSymbolAddress(&pWv, g_Wv);
    cudaGetSymbolAddress(&pWo, g_Wo);

    cudaFuncSetAttribute(gemm_f16_mma_kernel,
                         cudaFuncAttributeMaxDynamicSharedMemorySize, SMEM_TOTAL);

    // merged fp32 -> fp16 conversion: 1572864 float4s / 256 = 6144 blocks
    cvt_all_kernel<<<6144, 256>>>((const float4*)value, (const float4*)Wv,
                                  (const float4*)Wo,
                                  (uint2*)pA, (uint2*)pWv, (uint2*)pWo);

    const int grid = 2 * NBKT;   // 304 CTAs: 2 per SM (extras drain via stealing)

    // GEMM1: tmp = value @ Wv^T + bv -> out2, out3 + fp16(tmp) into g_T
    gemm_f16_mma_kernel<<<grid, NTHREADS, SMEM_TOTAL>>>(
        (const __half*)pA, (const __half*)pWv, bv,
        out2, out3, (__half*)pT, 0);

    // GEMM2: out1 = tmp @ Wo^T + bo
    gemm_f16_mma_kernel<<<grid, NTHREADS, SMEM_TOTAL>>>(
        (const __half*)pT, (const __half*)pWo, bo,
        out1, nullptr, nullptr, 1);
}

// round 17
// speedup vs baseline: 1.1782x; 1.1782x over previous
#include <cuda_runtime.h>
#include <cuda_fp16.h>
#include <cstdint>
#include <cstddef>

// ============================================================================
// Reduction (verified): tmp = value@Wv^T+bv -> out2,out3 ; out1 = tmp@Wo^T+bo
// Single-pass fp16 mma.sync (rel_err 4.15e-4 < 1e-3).
// R15 -> R16: revert to R14's proven GEMM shape (128x128 CTA, 4 warps,
// 64x64 warp tile = 33.4us/GEMM at the 4cyc/MMA roofline). Fuse BOTH GEMMs
// into one persistent kernel: GEMM1 tile queue -> per-row-panel ready flags
// -> GEMM2 tile queue. Idle second-wave SMs of GEMM1 start GEMM2 early,
// merging the two ragged tails into one.
// ============================================================================

#define MDIM 4096
#define NDIM 1024
#define KDIM 1024

#define BM 128
#define BN 128
#define BK 64              // 64 fp16 = 128B rows -> canonical SW128 swizzle
#define NTHREADS 128       // 4 warps: 2(m) x 2(n), warp tile 64x64
#define NCHUNK (KDIM / BK) // 16
#define NSTAGE 3
#define NPANEL (MDIM / BM)             // 32
#define TILES  ((MDIM / BM) * (NDIM / BN))  // 256
#define TPP    (NDIM / BN)             // 8 tiles per row panel

#define A_OFF 0
#define B_OFF (BM * 128)                       // 16384
#define STAGE_BYTES (BM * 128 + BN * 128)      // 32768
#define SMEM_TOTAL (NSTAGE * STAGE_BYTES)      // 98304 -> 2 CTAs/SM

// ---------------- device scratch (no runtime alloc allowed) ----------------
__device__ __half g_A[MDIM * KDIM];    // fp16(value)
__device__ __half g_T[MDIM * KDIM];    // fp16(tmp)
__device__ __half g_Wv[NDIM * KDIM];
__device__ __half g_Wo[NDIM * KDIM];

// scheduler state: [0]=g1 counter, [1]=g2 counter, [2..33]=panel done counts
__device__ uint32_t g_sched[40];

// ---------------- PTX helpers (plain-target legal, sm_80+) -----------------
__device__ __forceinline__ uint32_t smem_u32(const void* p) {
    uint32_t a;
    asm("{ .reg .u64 t; cvta.to.shared.u64 t, %1; cvt.u32.u64 %0, t; }" : "=r"(a) : "l"(p));
    return a;
}
__device__ __forceinline__ void cp_async16(uint32_t dst, const void* src) {
    asm volatile("cp.async.cg.shared.global [%0], [%1], 16;" :: "r"(dst), "l"(src));
}
#define CP_COMMIT() asm volatile("cp.async.commit_group;")
#define CP_WAIT1()  asm volatile("cp.async.wait_group 1;")
#define CP_WAIT0()  asm volatile("cp.async.wait_group 0;")

__device__ __forceinline__ void ldsm_x4(uint32_t* r, uint32_t addr) {
    asm volatile("ldmatrix.sync.aligned.m8n8.x4.shared.b16 {%0,%1,%2,%3}, [%4];"
                 : "=r"(r[0]), "=r"(r[1]), "=r"(r[2]), "=r"(r[3]) : "r"(addr));
}
__device__ __forceinline__ void mma_f16(float* d, const uint32_t* a, const uint32_t* b) {
    asm volatile(
        "mma.sync.aligned.m16n8k16.row.col.f32.f16.f16.f32 "
        "{%0,%1,%2,%3}, {%4,%5,%6,%7}, {%8,%9}, {%0,%1,%2,%3};"
        : "+f"(d[0]), "+f"(d[1]), "+f"(d[2]), "+f"(d[3])
        : "r"(a[0]), "r"(a[1]), "r"(a[2]), "r"(a[3]), "r"(b[0]), "r"(b[1]));
}

// SW128 swizzle on 128B rows: 16B chunk index XOR (row & 7)
__device__ __forceinline__ uint32_t swz(int row, int ch) {
    return (uint32_t)(row * 128 + ((ch ^ (row & 7)) << 4));
}

// ---------------- convert kernel: fp32 -> fp16 (+ optional sched reset) ----
__global__ void cvt_fp16_kernel(const float4* __restrict__ x, uint2* __restrict__ h,
                                int do_reset)
{
    int i = blockIdx.x * blockDim.x + threadIdx.x;
    if (do_reset && blockIdx.x == 0 && threadIdx.x < 40)
        g_sched[threadIdx.x] = 0;      // consumed only by the NEXT launch (stream order)
    float4 v = x[i];
    __half2 p0 = __floats2half2_rn(v.x, v.y);
    __half2 p1 = __floats2half2_rn(v.z, v.w);
    uint2 o;
    o.x = *(uint32_t*)&p0;
    o.y = *(uint32_t*)&p1;
    h[i] = o;
}

// ---------------- one 128x128 GEMM tile (R14-proven mainloop) --------------
__device__ __forceinline__ void gemm_tile(
    uint32_t sbase, const __half* __restrict__ Abase, const __half* __restrict__ Bbase,
    const float* __restrict__ bias, float* __restrict__ C0, float* __restrict__ C1,
    __half* __restrict__ TH, int tm, int tn, int tid, int wid, int lane)
{
    const int mbase = (wid & 1) * 64;
    const int nbase = (wid >> 1) * 64;

    const char* gA = (const char*)Abase + (size_t)(tm * BM) * (KDIM * 2);
    const char* gB = (const char*)Bbase + (size_t)(tn * BN) * (KDIM * 2);

    auto prefetch = [&](int c, int stage) {
        const uint32_t sb = sbase + stage * STAGE_BYTES;
        const size_t kb = (size_t)c * 128;
        #pragma unroll
        for (int t = 0; t < 8; t++) {        // A: 128 rows x 8 chunks = 1024
            int i = tid + t * NTHREADS;
            int r = i >> 3, ch = i & 7;
            cp_async16(sb + A_OFF + swz(r, ch),
                       gA + (size_t)r * (KDIM * 2) + kb + ch * 16);
        }
        #pragma unroll
        for (int t = 0; t < 8; t++) {        // B: 128 rows x 8 chunks = 1024
            int i = tid + t * NTHREADS;
            int r = i >> 3, ch = i & 7;
            cp_async16(sb + B_OFF + swz(r, ch),
                       gB + (size_t)r * (KDIM * 2) + kb + ch * 16);
        }
        CP_COMMIT();
    };

    float acc[4][8][4];
    #pragma unroll
    for (int mi = 0; mi < 4; mi++)
        #pragma unroll
        for (int ni = 0; ni < 8; ni++)
            #pragma unroll
            for (int j = 0; j < 4; j++)
                acc[mi][ni][j] = 0.0f;

    prefetch(0, 0);
    prefetch(1, 1);

    const int a_row = lane & 15;
    const int a_ch  = lane >> 4;
    const int b_row = lane & 7;
    const int b_ch  = (lane >> 3) & 1;
    const int b_nj  = lane >> 4;

    for (int c = 0; c < NCHUNK; c++) {
        if (c < NCHUNK - 1) { CP_WAIT1(); } else { CP_WAIT0(); }
        __syncthreads();
        if (c + 2 < NCHUNK) prefetch(c + 2, (c + 2) % NSTAGE);

        const uint32_t sb = sbase + (c % NSTAGE) * STAGE_BYTES;
        const uint32_t aS = sb + A_OFF, bS = sb + B_OFF;

        #pragma unroll
        for (int ks = 0; ks < 4; ks++) {
            uint32_t ah[4][4], bh[8][2];
            #pragma unroll
            for (int mi = 0; mi < 4; mi++) {
                int mrow = mbase + mi * 16 + a_row;
                ldsm_x4(ah[mi], aS + swz(mrow, 2 * ks + a_ch));
            }
            #pragma unroll
            for (int nj = 0; nj < 4; nj++) {
                uint32_t r4[4];
                int nrow = nbase + (nj * 2 + b_nj) * 8 + b_row;
                ldsm_x4(r4, bS + swz(nrow, 2 * ks + b_ch));
                bh[nj * 2 + 0][0] = r4[0]; bh[nj * 2 + 0][1] = r4[1];
                bh[nj * 2 + 1][0] = r4[2]; bh[nj * 2 + 1][1] = r4[3];
            }
            #pragma unroll
            for (int mi = 0; mi < 4; mi++)
                #pragma unroll
                for (int ni = 0; ni < 8; ni++)
                    mma_f16(acc[mi][ni], ah[mi], bh[ni]);
        }
    }

    const int erow = lane >> 2;
    const int ecol = 2 * (lane & 3);
    #pragma unroll
    for (int mi = 0; mi < 4; mi++) {
        #pragma unroll
        for (int ni = 0; ni < 8; ni++) {
            int gr0 = tm * BM + mbase + mi * 16 + erow;
            int gc  = tn * BN + nbase + ni * 8 + ecol;
            float b0 = bias[gc], b1 = bias[gc + 1];
            float2 v0 = { acc[mi][ni][0] + b0, acc[mi][ni][1] + b1 };
            float2 v1 = { acc[mi][ni][2] + b0, acc[mi][ni][3] + b1 };
            size_t o0 = (size_t)gr0 * NDIM + gc;
            size_t o1 = (size_t)(gr0 + 8) * NDIM + gc;
            *(float2*)(C0 + o0) = v0;
            *(float2*)(C0 + o1) = v1;
            if (C1) {
                *(float2*)(C1 + o0) = v0;
                *(float2*)(C1 + o1) = v1;
            }
            if (TH) {
                __half2 h0 = __floats2half2_rn(v0.x, v0.y);
                __half2 h1 = __floats2half2_rn(v1.x, v1.y);
                *(__half2*)(TH + o0) = h0;
                *(__half2*)(TH + o1) = h1;
            }
        }
    }
}

// ---------------- fused persistent dual-GEMM kernel ----------------
__global__ __launch_bounds__(NTHREADS, 2)
void fused_gemm_kernel(const float* __restrict__ bv,
                       float* __restrict__ out2,
                       float* __restrict__ out3,
                       const float* __restrict__ bo,
                       float* __restrict__ out1)
{
    extern __shared__ char smem[];
    __shared__ uint32_t sh_tile;
    const uint32_t sbase = smem_u32(smem);
    const int tid  = threadIdx.x;
    const int wid  = tid >> 5;
    const int lane = tid & 31;

    // ---------- phase 1: tmp = A @ Wv^T + bv ----------
    for (;;) {
        if (tid == 0) sh_tile = atomicAdd(&g_sched[0], 1u);
        __syncthreads();
        uint32_t t = sh_tile;
        if (t >= TILES) break;
        int tm = t >> 3, tn = t & (TPP - 1);   // row-panel-major order
        gemm_tile(sbase, g_A, g_Wv, bv, out2, out3, g_T, tm, tn, tid, wid, lane);
        __threadfence();                        // every storing thread fences
        __syncthreads();
        if (tid == 0) atomicAdd(&g_sched[2 + tm], 1u);  // publish panel progress
    }

    // ---------- phase 2: out1 = tmp @ Wo^T + bo ----------
    for (;;) {
        if (tid == 0) sh_tile = atomicAdd(&g_sched[1], 1u);
        __syncthreads();
        uint32_t t = sh_tile;
        if (t >= TILES) break;
        int tm = t >> 3, tn = t & (TPP - 1);
        if (tid == 0) {                         // wait for tmp row panel tm
            while (*(volatile uint32_t*)&g_sched[2 + tm] < TPP)
                __nanosleep(64);
            __threadfence();
        }
        __syncthreads();
        gemm_tile(sbase, g_T, g_Wo, bo, out1, nullptr, nullptr, tm, tn, tid, wid, lane);
    }
}

// ---------------- launch ----------------
extern "C" void kernel_launch(void* const* d_in, const int* in_sizes, int n_in,
                              void* d_out, int out_size)
{
    // Inputs: query, key, value, Wq, bq, Wk, bk, Wv, bv, Wo, bo
    const float* value = (const float*)d_in[2];
    const float* Wv    = (const float*)d_in[7];
    const float* bv    = (const float*)d_in[8];
    const float* Wo    = (const float*)d_in[9];
    const float* bo    = (const float*)d_in[10];

    float* out1 = (float*)d_out;
    float* out2 = out1 + (size_t)MDIM * NDIM;
    float* out3 = out2 + (size_t)MDIM * NDIM;

    void *pA, *pT, *pWv, *pWo;
    cudaGetSymbolAddress(&pA,  g_A);
    cudaGetSymbolAddress(&pT,  g_T);
    cudaGetSymbolAddress(&pWv, g_Wv);
    cudaGetSymbolAddress(&pWo, g_Wo);

    cudaFuncSetAttribute(fused_gemm_kernel,
                         cudaFuncAttributeMaxDynamicSharedMemorySize, SMEM_TOTAL);

    // fp32 -> fp16 conversions (value cvt also resets the scheduler state,
    // which is only read by the later, stream-ordered fused kernel)
    cvt_fp16_kernel<<<4096, 256>>>((const float4*)value, (uint2*)pA, 1);
    cvt_fp16_kernel<<<1024, 256>>>((const float4*)Wv, (uint2*)pWv, 0);
    cvt_fp16_kernel<<<1024, 256>>>((const float4*)Wo, (uint2*)pWo, 0);

    // persistent fused dual-GEMM: 304 CTAs (2 per SM), work-stealing queues.
    fused_gemm_kernel<<<304, NTHREADS, SMEM_TOTAL>>>(bv, out2, out3, bo, out1);
}